// round 1
// baseline (speedup 1.0000x reference)
#include <cuda_runtime.h>

// ConsensusAttention: levels [B=8, N=1024, L=6, D=128] fp32.
// q = levels, k = levels / max(||levels||, 1e-12)
// sim[b,l,i,j] = (q_i . k_j) / sqrt(D); sim[i,i] = -0.0005
// tokens farther than radius 2.0 on the 32x32 grid are masked to -inf
// => each token attends to at most 13 neighbors (dy^2+dx^2 <= 4).
// out[b,i,l,d] = softmax_j(sim) @ levels[b,j,l,d]

#define B_DIM 8
#define N_TOK 1024
#define L_DIM 6
#define D_DIM 128
#define ROWS (B_DIM * N_TOK * L_DIM)   // 49152
#define ROW_STRIDE (L_DIM * D_DIM)     // 768 floats between consecutive j

__device__ float g_invnorm[ROWS];

// Kernel 1: per-row inverse norms. One warp per (b, j, l) row.
__global__ __launch_bounds__(256) void norm_kernel(const float* __restrict__ in) {
    int warp = (blockIdx.x * 256 + threadIdx.x) >> 5;
    int lane = threadIdx.x & 31;
    if (warp >= ROWS) return;
    float4 v = ((const float4*)(in + (size_t)warp * D_DIM))[lane];
    float s = v.x * v.x + v.y * v.y + v.z * v.z + v.w * v.w;
    #pragma unroll
    for (int m = 16; m; m >>= 1) s += __shfl_xor_sync(0xffffffffu, s, m);
    if (lane == 0) g_invnorm[warp] = 1.0f / fmaxf(sqrtf(s), 1e-12f);
}

// Kernel 2: local attention. 8 lanes per token, 4 tokens per warp.
// Each lane owns 16 of the 128 d-elements (4 float4s, lane-interleaved so
// each load instruction per group covers a contiguous 128B chunk).
__global__ __launch_bounds__(256) void attn_kernel(const float* __restrict__ in,
                                                   float* __restrict__ out) {
    const int gid  = (blockIdx.x * 256 + threadIdx.x) >> 3;  // token id, 0..49151
    const int lane = threadIdx.x & 7;

    const int i  = gid & (N_TOK - 1);
    const int bl = gid >> 10;          // b * L + l
    const int b  = bl / L_DIM;
    const int l  = bl - b * L_DIM;
    const int y  = i >> 5;
    const int x  = i & 31;

    const float* base = in + ((size_t)b * N_TOK * L_DIM + l) * D_DIM;  // + j*ROW_STRIDE
    const float* invb = g_invnorm + (b * N_TOK * L_DIM + l);           // + j*L_DIM

    // Load q (self row)
    const float4* qr = (const float4*)(base + (size_t)i * ROW_STRIDE);
    float4 q0 = qr[lane], q1 = qr[8 + lane], q2 = qr[16 + lane], q3 = qr[24 + lane];

    // Self term: sim = -0.0005 exactly (reference constant), value = q.
    float wself = __expf(-0.0005f);
    float ssum = wself;
    float4 a0, a1, a2, a3;
    a0.x = wself * q0.x; a0.y = wself * q0.y; a0.z = wself * q0.z; a0.w = wself * q0.w;
    a1.x = wself * q1.x; a1.y = wself * q1.y; a1.z = wself * q1.z; a1.w = wself * q1.w;
    a2.x = wself * q2.x; a2.y = wself * q2.y; a2.z = wself * q2.z; a2.w = wself * q2.w;
    a3.x = wself * q3.x; a3.y = wself * q3.y; a3.z = wself * q3.z; a3.w = wself * q3.w;

    // 12 non-self neighbors with dy^2 + dx^2 <= 4
    const int dys[12] = {-2, -1, -1, -1,  0,  0, 0, 0, 1, 1, 1, 2};
    const int dxs[12] = { 0, -1,  0,  1, -2, -1, 1, 2,-1, 0, 1, 0};
    const float RSQRT_D = 0.08838834764831845f;  // 1/sqrt(128)

    #pragma unroll
    for (int t = 0; t < 12; t++) {
        int yy = y + dys[t];
        int xx = x + dxs[t];
        if ((unsigned)yy < 32u && (unsigned)xx < 32u) {
            int j = (yy << 5) | xx;
            const float4* r = (const float4*)(base + (size_t)j * ROW_STRIDE);
            float4 v0 = r[lane], v1 = r[8 + lane], v2 = r[16 + lane], v3 = r[24 + lane];

            float dp = q0.x * v0.x + q0.y * v0.y + q0.z * v0.z + q0.w * v0.w
                     + q1.x * v1.x + q1.y * v1.y + q1.z * v1.z + q1.w * v1.w
                     + q2.x * v2.x + q2.y * v2.y + q2.z * v2.z + q2.w * v2.w
                     + q3.x * v3.x + q3.y * v3.y + q3.z * v3.z + q3.w * v3.w;
            // 8-lane butterfly reduce (serves all 4 tokens in the warp at once)
            dp += __shfl_xor_sync(0xffffffffu, dp, 1);
            dp += __shfl_xor_sync(0xffffffffu, dp, 2);
            dp += __shfl_xor_sync(0xffffffffu, dp, 4);

            float sim = dp * invb[j * L_DIM] * RSQRT_D;
            float w = __expf(sim);   // sims are O(1); no max-subtraction needed
            ssum += w;
            a0.x += w * v0.x; a0.y += w * v0.y; a0.z += w * v0.z; a0.w += w * v0.w;
            a1.x += w * v1.x; a1.y += w * v1.y; a1.z += w * v1.z; a1.w += w * v1.w;
            a2.x += w * v2.x; a2.y += w * v2.y; a2.z += w * v2.z; a2.w += w * v2.w;
            a3.x += w * v3.x; a3.y += w * v3.y; a3.z += w * v3.z; a3.w += w * v3.w;
        }
    }

    float inv = 1.0f / ssum;
    a0.x *= inv; a0.y *= inv; a0.z *= inv; a0.w *= inv;
    a1.x *= inv; a1.y *= inv; a1.z *= inv; a1.w *= inv;
    a2.x *= inv; a2.y *= inv; a2.z *= inv; a2.w *= inv;
    a3.x *= inv; a3.y *= inv; a3.z *= inv; a3.w *= inv;

    float4* o = (float4*)(out + ((size_t)(b * N_TOK + i) * L_DIM + l) * D_DIM);
    o[lane] = a0; o[8 + lane] = a1; o[16 + lane] = a2; o[24 + lane] = a3;
}

extern "C" void kernel_launch(void* const* d_in, const int* in_sizes, int n_in,
                              void* d_out, int out_size) {
    const float* in = (const float*)d_in[0];
    float* out = (float*)d_out;
    norm_kernel<<<ROWS / 8, 256>>>(in);          // 6144 blocks, 8 warps each
    attn_kernel<<<ROWS / 32, 256>>>(in, out);    // 1536 blocks, 32 tokens each
}

// round 2
// speedup vs baseline: 1.0767x; 1.0767x over previous
#include <cuda_runtime.h>

// ConsensusAttention: levels [B=8, N=1024, L=6, D=128] fp32.
// Local attention: each token attends to <=13 neighbors (dy^2+dx^2 <= 4 on 32x32 grid),
// self sim fixed at -0.0005, others = (q_i . k_j)/sqrt(D) with k = normalized levels.

#define B_DIM 8
#define N_TOK 1024
#define L_DIM 6
#define D_DIM 128
#define ROWS (B_DIM * N_TOK * L_DIM)   // 49152
#define ROW_STRIDE (L_DIM * D_DIM)     // 768 floats between consecutive j

__device__ float g_invnorm[ROWS];

// Kernel 1: per-row inverse norms. One warp per (b, j, l) row.
__global__ __launch_bounds__(256) void norm_kernel(const float* __restrict__ in) {
    int warp = (blockIdx.x * 256 + threadIdx.x) >> 5;
    int lane = threadIdx.x & 31;
    if (warp >= ROWS) return;
    float4 v = ((const float4*)(in + (size_t)warp * D_DIM))[lane];
    float s = v.x * v.x + v.y * v.y + v.z * v.z + v.w * v.w;
    #pragma unroll
    for (int m = 16; m; m >>= 1) s += __shfl_xor_sync(0xffffffffu, s, m);
    if (lane == 0) g_invnorm[warp] = 1.0f / fmaxf(sqrtf(s), 1e-12f);
}

// Kernel 2: local attention, latency-optimized 3-phase structure.
// 8 lanes per token, 4 tokens per warp. Each lane owns 16 of 128 d-elements.
__global__ __launch_bounds__(256, 2) void attn_kernel(const float* __restrict__ in,
                                                      float* __restrict__ out) {
    const int gid  = (blockIdx.x * 256 + threadIdx.x) >> 3;  // token id, 0..49151
    const int lane = threadIdx.x & 7;

    const int i  = gid & (N_TOK - 1);
    const int bl = gid >> 10;          // b * L + l
    const int b  = bl / L_DIM;
    const int l  = bl - b * L_DIM;
    const int y  = i >> 5;
    const int x  = i & 31;

    const float* base = in + ((size_t)b * N_TOK * L_DIM + l) * D_DIM;  // + j*ROW_STRIDE
    const float* invb = g_invnorm + (b * N_TOK * L_DIM + l);           // + j*L_DIM

    // Load q (self row)
    const float4* qr = (const float4*)(base + (size_t)i * ROW_STRIDE);
    float4 q0 = qr[lane], q1 = qr[8 + lane], q2 = qr[16 + lane], q3 = qr[24 + lane];

    // 12 non-self neighbors with dy^2 + dx^2 <= 4
    const int dys[12] = {-2, -1, -1, -1,  0,  0, 0, 0, 1, 1, 1, 2};
    const int dxs[12] = { 0, -1,  0,  1, -2, -1, 1, 2,-1, 0, 1, 0};
    const float RSQRT_D = 0.08838834764831845f;  // 1/sqrt(128)

    // ---- Phase A: batched loads + partial dot products (max MLP) ----
    int   joff[12];     // row index of neighbor (clamped to self when OOB)
    float valid[12];    // 1.0 if in-bounds else 0.0
    float dp[12];
    float nrm[12];

    #pragma unroll
    for (int t = 0; t < 12; t++) {
        int yy = y + dys[t];
        int xx = x + dxs[t];
        bool ok = ((unsigned)yy < 32u) & ((unsigned)xx < 32u);
        int j = ok ? ((yy << 5) | xx) : i;   // clamp OOB to self (address always valid)
        joff[t]  = j;
        valid[t] = ok ? 1.0f : 0.0f;
        nrm[t]   = invb[j * L_DIM];          // scalar prefetch (broadcast across 8 lanes)
        const float4* r = (const float4*)(base + (size_t)j * ROW_STRIDE);
        float4 v0 = r[lane], v1 = r[8 + lane], v2 = r[16 + lane], v3 = r[24 + lane];
        dp[t] = q0.x * v0.x + q0.y * v0.y + q0.z * v0.z + q0.w * v0.w
              + q1.x * v1.x + q1.y * v1.y + q1.z * v1.z + q1.w * v1.w
              + q2.x * v2.x + q2.y * v2.y + q2.z * v2.z + q2.w * v2.w
              + q3.x * v3.x + q3.y * v3.y + q3.z * v3.z + q3.w * v3.w;
    }

    // ---- Phase R: 12 independent shuffle-reduction chains, then exps ----
    #pragma unroll
    for (int t = 0; t < 12; t++) dp[t] += __shfl_xor_sync(0xffffffffu, dp[t], 1);
    #pragma unroll
    for (int t = 0; t < 12; t++) dp[t] += __shfl_xor_sync(0xffffffffu, dp[t], 2);
    #pragma unroll
    for (int t = 0; t < 12; t++) dp[t] += __shfl_xor_sync(0xffffffffu, dp[t], 4);

    float w[12];
    float ssum = __expf(-0.0005f);  // self term weight
    #pragma unroll
    for (int t = 0; t < 12; t++) {
        float sim = dp[t] * nrm[t] * RSQRT_D;
        w[t] = valid[t] * __expf(sim);   // sims are O(1); no max-subtraction needed
        ssum += w[t];
    }

    // ---- Phase B: re-load v tiles (L1-hot) and accumulate ----
    float wself = __expf(-0.0005f);
    float4 a0, a1, a2, a3;
    a0.x = wself * q0.x; a0.y = wself * q0.y; a0.z = wself * q0.z; a0.w = wself * q0.w;
    a1.x = wself * q1.x; a1.y = wself * q1.y; a1.z = wself * q1.z; a1.w = wself * q1.w;
    a2.x = wself * q2.x; a2.y = wself * q2.y; a2.z = wself * q2.z; a2.w = wself * q2.w;
    a3.x = wself * q3.x; a3.y = wself * q3.y; a3.z = wself * q3.z; a3.w = wself * q3.w;

    #pragma unroll
    for (int t = 0; t < 12; t++) {
        const float4* r = (const float4*)(base + (size_t)joff[t] * ROW_STRIDE);
        float4 v0 = r[lane], v1 = r[8 + lane], v2 = r[16 + lane], v3 = r[24 + lane];
        float wt = w[t];
        a0.x += wt * v0.x; a0.y += wt * v0.y; a0.z += wt * v0.z; a0.w += wt * v0.w;
        a1.x += wt * v1.x; a1.y += wt * v1.y; a1.z += wt * v1.z; a1.w += wt * v1.w;
        a2.x += wt * v2.x; a2.y += wt * v2.y; a2.z += wt * v2.z; a2.w += wt * v2.w;
        a3.x += wt * v3.x; a3.y += wt * v3.y; a3.z += wt * v3.z; a3.w += wt * v3.w;
    }

    float inv = 1.0f / ssum;
    a0.x *= inv; a0.y *= inv; a0.z *= inv; a0.w *= inv;
    a1.x *= inv; a1.y *= inv; a1.z *= inv; a1.w *= inv;
    a2.x *= inv; a2.y *= inv; a2.z *= inv; a2.w *= inv;
    a3.x *= inv; a3.y *= inv; a3.z *= inv; a3.w *= inv;

    float4* o = (float4*)(out + ((size_t)(b * N_TOK + i) * L_DIM + l) * D_DIM);
    o[lane] = a0; o[8 + lane] = a1; o[16 + lane] = a2; o[24 + lane] = a3;
}

extern "C" void kernel_launch(void* const* d_in, const int* in_sizes, int n_in,
                              void* d_out, int out_size) {
    const float* in = (const float*)d_in[0];
    float* out = (float*)d_out;
    norm_kernel<<<ROWS / 8, 256>>>(in);          // 6144 blocks, 8 warps each
    attn_kernel<<<ROWS / 32, 256>>>(in, out);    // 1536 blocks, 32 tokens each
}

// round 3
// speedup vs baseline: 1.6492x; 1.5317x over previous
#include <cuda_runtime.h>

// ConsensusAttention: levels [B=8, N=1024, L=6, D=128] fp32.
// Local attention: each token attends to <=13 neighbors (dy^2+dx^2 <= 4 on 32x32 grid),
// self sim fixed at -0.0005, others = (q_i . k_j)/sqrt(D) with k = normalized levels.

#define B_DIM 8
#define N_TOK 1024
#define L_DIM 6
#define D_DIM 128
#define ROWS (B_DIM * N_TOK * L_DIM)   // 49152
#define ROW_STRIDE (L_DIM * D_DIM)     // 768 floats between consecutive j

__device__ float g_invnorm[ROWS];

// Kernel 1: per-row inverse norms. One warp per (b, j, l) row.
__global__ __launch_bounds__(256) void norm_kernel(const float* __restrict__ in) {
    int warp = (blockIdx.x * 256 + threadIdx.x) >> 5;
    int lane = threadIdx.x & 31;
    float4 v = ((const float4*)(in + (size_t)warp * D_DIM))[lane];
    float s = v.x * v.x + v.y * v.y + v.z * v.z + v.w * v.w;
    #pragma unroll
    for (int m = 16; m; m >>= 1) s += __shfl_xor_sync(0xffffffffu, s, m);
    if (lane == 0) g_invnorm[warp] = 1.0f / fmaxf(sqrtf(s), 1e-12f);
}

// Kernel 2: local attention. 16 lanes per token (2 tokens/warp), lane owns 8 of
// 128 d-elements. Neighbor pairs are software-pipelined with a double buffer so
// ~8 LDG.128 stay in flight while the previous pair reduces/accumulates.
// v tiles live in registers from dot-product through accumulation (single read).
__global__ __launch_bounds__(256, 3) void attn_kernel(const float* __restrict__ in,
                                                      float* __restrict__ out) {
    const int tid  = threadIdx.x;
    const int gid  = (blockIdx.x * 256 + tid) >> 4;  // token id, 0..49151
    const int lane = tid & 15;

    const int i  = gid & (N_TOK - 1);
    const int bl = gid >> 10;          // b * L + l
    const int b  = bl / L_DIM;
    const int l  = bl - b * L_DIM;
    const int y  = i >> 5;
    const int x  = i & 31;

    const float* base = in + ((size_t)b * N_TOK * L_DIM + l) * D_DIM;  // + j*ROW_STRIDE
    const float* invb = g_invnorm + (b * N_TOK * L_DIM + l);           // + j*L_DIM

    // q (self row): lane owns elements [4*lane..4*lane+3] and [64+4*lane..]
    const float4* qr = (const float4*)(base + (size_t)i * ROW_STRIDE);
    const float4 q0 = qr[lane], q1 = qr[16 + lane];

    // Self term: sim = -0.0005 exactly; value = q.
    const float wself = __expf(-0.0005f);
    float ssum = wself;
    float4 a0, a1;
    a0.x = wself * q0.x; a0.y = wself * q0.y; a0.z = wself * q0.z; a0.w = wself * q0.w;
    a1.x = wself * q1.x; a1.y = wself * q1.y; a1.z = wself * q1.z; a1.w = wself * q1.w;

    // 12 non-self neighbors with dy^2 + dx^2 <= 4
    const int dys[12] = {-2, -1, -1, -1,  0,  0, 0, 0, 1, 1, 1, 2};
    const int dxs[12] = { 0, -1,  0,  1, -2, -1, 1, 2,-1, 0, 1, 0};
    const float RSQRT_D = 0.08838834764831845f;  // 1/sqrt(128)

    float4 vb[2][2][2];   // [parity][neighbor-in-pair][d-chunk]
    float  sc[2][2];      // dp scale: invnorm/sqrt(D), or 0 if OOB
    float  bi[2][2];      // sim bias: 0, or -60 if OOB (exp -> 0)

    // Prologue: load pair 0
    #pragma unroll
    for (int n = 0; n < 2; n++) {
        int yy = y + dys[n], xx = x + dxs[n];
        bool ok = ((unsigned)yy < 32u) & ((unsigned)xx < 32u);
        int j = ok ? ((yy << 5) | xx) : i;
        sc[0][n] = ok ? invb[j * L_DIM] * RSQRT_D : 0.0f;
        bi[0][n] = ok ? 0.0f : -60.0f;
        const float4* r = (const float4*)(base + (size_t)j * ROW_STRIDE);
        vb[0][n][0] = r[lane];
        vb[0][n][1] = r[16 + lane];
    }

    #pragma unroll
    for (int p = 0; p < 6; p++) {
        const int cur = p & 1, nxt = cur ^ 1;

        // Prefetch next pair's tiles (hides L1/L2 latency under this pair's math)
        if (p < 5) {
            #pragma unroll
            for (int n = 0; n < 2; n++) {
                int t = (p + 1) * 2 + n;
                int yy = y + dys[t], xx = x + dxs[t];
                bool ok = ((unsigned)yy < 32u) & ((unsigned)xx < 32u);
                int j = ok ? ((yy << 5) | xx) : i;
                sc[nxt][n] = ok ? invb[j * L_DIM] * RSQRT_D : 0.0f;
                bi[nxt][n] = ok ? 0.0f : -60.0f;
                const float4* r = (const float4*)(base + (size_t)j * ROW_STRIDE);
                vb[nxt][n][0] = r[lane];
                vb[nxt][n][1] = r[16 + lane];
            }
        }

        // Partial dot products for the current pair (v already in registers)
        float dpn[2];
        #pragma unroll
        for (int n = 0; n < 2; n++) {
            float4 v0 = vb[cur][n][0], v1 = vb[cur][n][1];
            dpn[n] = q0.x * v0.x + q0.y * v0.y + q0.z * v0.z + q0.w * v0.w
                   + q1.x * v1.x + q1.y * v1.y + q1.z * v1.z + q1.w * v1.w;
        }

        // 16-lane butterfly reduce, two independent chains interleaved
        #pragma unroll
        for (int m = 1; m < 16; m <<= 1) {
            dpn[0] += __shfl_xor_sync(0xffffffffu, dpn[0], m);
            dpn[1] += __shfl_xor_sync(0xffffffffu, dpn[1], m);
        }

        // exp + accumulate (v still in registers; sims O(1), no max-subtract)
        #pragma unroll
        for (int n = 0; n < 2; n++) {
            float w = __expf(fmaf(dpn[n], sc[cur][n], bi[cur][n]));
            ssum += w;
            float4 v0 = vb[cur][n][0], v1 = vb[cur][n][1];
            a0.x += w * v0.x; a0.y += w * v0.y; a0.z += w * v0.z; a0.w += w * v0.w;
            a1.x += w * v1.x; a1.y += w * v1.y; a1.z += w * v1.z; a1.w += w * v1.w;
        }
    }

    const float inv = 1.0f / ssum;
    a0.x *= inv; a0.y *= inv; a0.z *= inv; a0.w *= inv;
    a1.x *= inv; a1.y *= inv; a1.z *= inv; a1.w *= inv;

    float4* o = (float4*)(out + ((size_t)(b * N_TOK + i) * L_DIM + l) * D_DIM);
    o[lane] = a0;
    o[16 + lane] = a1;
}

extern "C" void kernel_launch(void* const* d_in, const int* in_sizes, int n_in,
                              void* d_out, int out_size) {
    const float* in = (const float*)d_in[0];
    float* out = (float*)d_out;
    norm_kernel<<<ROWS / 8, 256>>>(in);          // 6144 blocks, 8 warps each
    attn_kernel<<<ROWS / 16, 256>>>(in, out);    // 3072 blocks, 16 tokens each
}

// round 4
// speedup vs baseline: 1.8592x; 1.1273x over previous
#include <cuda_runtime.h>

// ConsensusAttention: levels [B=8, N=1024, L=6, D=128] fp32.
// Local attention: each token attends to <=13 neighbors (dy^2+dx^2 <= 4 on 32x32 grid),
// self sim fixed at -0.0005, others = (q_i . k_j)/sqrt(D) with k = normalized levels.

#define B_DIM 8
#define N_TOK 1024
#define L_DIM 6
#define D_DIM 128
#define ROWS (B_DIM * N_TOK * L_DIM)   // 49152
#define ROW_STRIDE (L_DIM * D_DIM)     // 768 floats between consecutive j
#define ROW_U2 (ROW_STRIDE * 4 / 16)   // 192 ulonglong2 per row

__device__ float g_invnorm[ROWS];

// ---- packed f32x2 helpers (Blackwell FFMA2 path, PTX-only) ----
__device__ __forceinline__ unsigned long long pk2(float lo, float hi) {
    unsigned long long r;
    asm("mov.b64 %0, {%1, %2};" : "=l"(r) : "f"(lo), "f"(hi));
    return r;
}
__device__ __forceinline__ unsigned long long pk_fma(unsigned long long a,
                                                     unsigned long long b,
                                                     unsigned long long c) {
    unsigned long long d;
    asm("fma.rn.f32x2 %0, %1, %2, %3;" : "=l"(d) : "l"(a), "l"(b), "l"(c));
    return d;
}
__device__ __forceinline__ unsigned long long pk_mul(unsigned long long a,
                                                     unsigned long long b) {
    unsigned long long d;
    asm("mul.rn.f32x2 %0, %1, %2;" : "=l"(d) : "l"(a), "l"(b));
    return d;
}
__device__ __forceinline__ float pk_hadd(unsigned long long a) {
    float lo, hi;
    asm("mov.b64 {%0, %1}, %2;" : "=f"(lo), "=f"(hi) : "l"(a));
    return lo + hi;
}

// Kernel 1: per-row inverse norms. One warp per (b, j, l) row.
__global__ __launch_bounds__(256) void norm_kernel(const float* __restrict__ in) {
    int warp = (blockIdx.x * 256 + threadIdx.x) >> 5;
    int lane = threadIdx.x & 31;
    float4 v = ((const float4*)(in + (size_t)warp * D_DIM))[lane];
    float s = v.x * v.x + v.y * v.y + v.z * v.z + v.w * v.w;
    #pragma unroll
    for (int m = 16; m; m >>= 1) s += __shfl_xor_sync(0xffffffffu, s, m);
    if (lane == 0) g_invnorm[warp] = 1.0f / fmaxf(sqrtf(s), 1e-12f);
}

// Kernel 2: local attention. 16 lanes/token (2 tokens/warp); lane owns 8 of
// 128 d-elements as 2 ulonglong2 (= 4 packed f32x2). Neighbor pairs are
// software-pipelined; dp + accumulate use packed FFMA2; neighbor addresses are
// compile-time constant offsets from the self row (OOB selects offset 0 and a
// -60 sim bias so exp -> ~0).
__global__ __launch_bounds__(256, 3) void attn_kernel(const float* __restrict__ in,
                                                      float* __restrict__ out) {
    const int tid  = threadIdx.x;
    const int gid  = (blockIdx.x * 256 + tid) >> 4;  // token id, 0..49151
    const int lane = tid & 15;

    const int i  = gid & (N_TOK - 1);
    const int bl = gid >> 10;          // b * L + l
    const int b  = bl / L_DIM;
    const int l  = bl - b * L_DIM;
    const int y  = i >> 5;
    const int x  = i & 31;

    // self row pointer; neighbor j = i + doff is at qr + doff*ROW_U2
    const ulonglong2* qr =
        (const ulonglong2*)(in + ((size_t)b * N_TOK * L_DIM + l) * D_DIM
                               + (size_t)i * ROW_STRIDE);
    const float* invp = g_invnorm + ((size_t)(b * N_TOK + i) * L_DIM + l);

    const ulonglong2 q0 = qr[lane], q1 = qr[16 + lane];

    // Self term: sim = -0.0005 exactly; value = q.
    const float wself = __expf(-0.0005f);
    float ssum = wself;
    const unsigned long long ws2 = pk2(wself, wself);
    unsigned long long a00 = pk_mul(ws2, q0.x);
    unsigned long long a01 = pk_mul(ws2, q0.y);
    unsigned long long a10 = pk_mul(ws2, q1.x);
    unsigned long long a11 = pk_mul(ws2, q1.y);

    // 12 non-self neighbors with dy^2 + dx^2 <= 4
    const int dys[12] = {-2, -1, -1, -1,  0,  0, 0, 0, 1, 1, 1, 2};
    const int dxs[12] = { 0, -1,  0,  1, -2, -1, 1, 2,-1, 0, 1, 0};
    const float RSQRT_D = 0.08838834764831845f;  // 1/sqrt(128)

    ulonglong2 vb[2][2][2];   // [parity][neighbor-in-pair][d-chunk]
    float      sc[2][2];      // dp scale: invnorm/sqrt(D)
    float      bi[2][2];      // sim bias: 0, or -60 if OOB (exp -> 0)

    // Prologue: load pair 0
    #pragma unroll
    for (int n = 0; n < 2; n++) {
        const int doff = dys[n] * 32 + dxs[n];           // compile-time constant
        bool ok = ((unsigned)(y + dys[n]) < 32u) & ((unsigned)(x + dxs[n]) < 32u);
        const int po = ok ? doff * ROW_U2 : 0;
        sc[0][n] = invp[ok ? doff * L_DIM : 0] * RSQRT_D;
        bi[0][n] = ok ? 0.0f : -60.0f;
        vb[0][n][0] = qr[po + lane];
        vb[0][n][1] = qr[po + 16 + lane];
    }

    #pragma unroll
    for (int p = 0; p < 6; p++) {
        const int cur = p & 1, nxt = cur ^ 1;

        // Prefetch next pair (hides L1/L2 latency under this pair's math)
        if (p < 5) {
            #pragma unroll
            for (int n = 0; n < 2; n++) {
                const int t = (p + 1) * 2 + n;
                const int doff = dys[t] * 32 + dxs[t];   // compile-time constant
                bool ok = ((unsigned)(y + dys[t]) < 32u) & ((unsigned)(x + dxs[t]) < 32u);
                const int po = ok ? doff * ROW_U2 : 0;
                sc[nxt][n] = invp[ok ? doff * L_DIM : 0] * RSQRT_D;
                bi[nxt][n] = ok ? 0.0f : -60.0f;
                vb[nxt][n][0] = qr[po + lane];
                vb[nxt][n][1] = qr[po + 16 + lane];
            }
        }

        // Packed partial dot products (4 FFMA2 each), then horizontal add
        float dpn[2];
        #pragma unroll
        for (int n = 0; n < 2; n++) {
            unsigned long long d2 = pk_mul(q0.x, vb[cur][n][0].x);
            d2 = pk_fma(q0.y, vb[cur][n][0].y, d2);
            d2 = pk_fma(q1.x, vb[cur][n][1].x, d2);
            d2 = pk_fma(q1.y, vb[cur][n][1].y, d2);
            dpn[n] = pk_hadd(d2);
        }

        // 16-lane butterfly reduce, two independent chains interleaved
        #pragma unroll
        for (int m = 1; m < 16; m <<= 1) {
            dpn[0] += __shfl_xor_sync(0xffffffffu, dpn[0], m);
            dpn[1] += __shfl_xor_sync(0xffffffffu, dpn[1], m);
        }

        // exp + packed accumulate (v still in registers)
        #pragma unroll
        for (int n = 0; n < 2; n++) {
            float w = __expf(fmaf(dpn[n], sc[cur][n], bi[cur][n]));
            ssum += w;
            const unsigned long long w2 = pk2(w, w);
            a00 = pk_fma(w2, vb[cur][n][0].x, a00);
            a01 = pk_fma(w2, vb[cur][n][0].y, a01);
            a10 = pk_fma(w2, vb[cur][n][1].x, a10);
            a11 = pk_fma(w2, vb[cur][n][1].y, a11);
        }
    }

    const float inv = 1.0f / ssum;
    const unsigned long long inv2 = pk2(inv, inv);
    ulonglong2 o0, o1;
    o0.x = pk_mul(a00, inv2);
    o0.y = pk_mul(a01, inv2);
    o1.x = pk_mul(a10, inv2);
    o1.y = pk_mul(a11, inv2);

    ulonglong2* orow = (ulonglong2*)(out + ((size_t)(b * N_TOK + i) * L_DIM + l) * D_DIM);
    orow[lane] = o0;
    orow[16 + lane] = o1;
}

extern "C" void kernel_launch(void* const* d_in, const int* in_sizes, int n_in,
                              void* d_out, int out_size) {
    const float* in = (const float*)d_in[0];
    float* out = (float*)d_out;
    norm_kernel<<<ROWS / 8, 256>>>(in);          // 6144 blocks, 8 warps each
    attn_kernel<<<ROWS / 16, 256>>>(in, out);    // 3072 blocks, 16 tokens each
}

// round 6
// speedup vs baseline: 1.9607x; 1.0546x over previous
#include <cuda_runtime.h>

// ConsensusAttention: levels [B=8, N=1024, L=6, D=128] fp32.
// Local attention: each token attends to <=13 neighbors (dy^2+dx^2 <= 4 on 32x32 grid),
// self sim fixed at -0.0005, others = (q_i . k_j)/sqrt(D) with k = normalized levels.
// Single fused kernel: neighbor norms computed in-flight (v already in registers),
// 4 interleaved shfl-butterfly reduction chains, softmax weight via one EX2.

#define B_DIM 8
#define N_TOK 1024
#define L_DIM 6
#define D_DIM 128
#define ROWS (B_DIM * N_TOK * L_DIM)   // 49152
#define ROW_STRIDE (L_DIM * D_DIM)     // 768 floats between consecutive j
#define ROW_U2 (ROW_STRIDE / 4)        // 192 ulonglong2 per row

// ---- packed f32x2 helpers (Blackwell FFMA2 path, PTX-only) ----
__device__ __forceinline__ unsigned long long pk2(float lo, float hi) {
    unsigned long long r;
    asm("mov.b64 %0, {%1, %2};" : "=l"(r) : "f"(lo), "f"(hi));
    return r;
}
__device__ __forceinline__ unsigned long long pk_fma(unsigned long long a,
                                                     unsigned long long b,
                                                     unsigned long long c) {
    unsigned long long d;
    asm("fma.rn.f32x2 %0, %1, %2, %3;" : "=l"(d) : "l"(a), "l"(b), "l"(c));
    return d;
}
__device__ __forceinline__ unsigned long long pk_mul(unsigned long long a,
                                                     unsigned long long b) {
    unsigned long long d;
    asm("mul.rn.f32x2 %0, %1, %2;" : "=l"(d) : "l"(a), "l"(b));
    return d;
}
__device__ __forceinline__ float pk_hadd(unsigned long long a) {
    float lo, hi;
    asm("mov.b64 {%0, %1}, %2;" : "=f"(lo), "=f"(hi) : "l"(a));
    return lo + hi;
}
__device__ __forceinline__ float rsqrt_approx(float x) {
    float r;
    asm("rsqrt.approx.f32 %0, %1;" : "=f"(r) : "f"(x));
    return r;
}
__device__ __forceinline__ float ex2_approx(float x) {
    float r;
    asm("ex2.approx.f32 %0, %1;" : "=f"(r) : "f"(x));
    return r;
}

// 16 lanes/token (2 tokens/warp); lane owns 8 of 128 d-elements as 2 ulonglong2
// (= 4 packed f32x2). Neighbor pairs are software-pipelined (double buffer);
// dp (q.v) and |v|^2 computed together with packed FFMA2; four independent
// butterfly chains reduce them across the 16 lanes.
__global__ __launch_bounds__(128, 6) void attn_kernel(const float* __restrict__ in,
                                                      float* __restrict__ out) {
    const int tid  = threadIdx.x;
    const int gid  = (blockIdx.x * 128 + tid) >> 4;  // token id, 0..49151
    const int lane = tid & 15;

    const int i  = gid & (N_TOK - 1);
    const int bl = gid >> 10;          // b * L + l
    const int b  = bl / L_DIM;
    const int l  = bl - b * L_DIM;
    const int y  = i >> 5;
    const int x  = i & 31;

    // self row pointer; neighbor j = i + doff is at qr + doff*ROW_U2
    const ulonglong2* qr =
        (const ulonglong2*)(in + ((size_t)b * N_TOK * L_DIM + l) * D_DIM
                               + (size_t)i * ROW_STRIDE);

    const ulonglong2 q0 = qr[lane], q1 = qr[16 + lane];

    // Self term: sim = -0.0005 exactly; value = q.
    const float wself = 0.9995001249791693f;   // exp(-0.0005)
    float ssum = wself;
    const unsigned long long ws2 = pk2(wself, wself);
    unsigned long long a00 = pk_mul(ws2, q0.x);
    unsigned long long a01 = pk_mul(ws2, q0.y);
    unsigned long long a10 = pk_mul(ws2, q1.x);
    unsigned long long a11 = pk_mul(ws2, q1.y);

    // 12 non-self neighbors with dy^2 + dx^2 <= 4
    const int dys[12] = {-2, -1, -1, -1,  0,  0, 0, 0, 1, 1, 1, 2};
    const int dxs[12] = { 0, -1,  0,  1, -2, -1, 1, 2,-1, 0, 1, 0};
    // sim->exp2 scale: (1/sqrt(128)) * log2(e)
    const float C_SC = 0.12751742119567576f;

    ulonglong2 vb[2][2][2];   // [parity][neighbor-in-pair][d-chunk]
    float      bi[2][2];      // exp2 bias: 0, or -100 if OOB (ex2 -> ~0)

    // Prologue: load pair 0
    #pragma unroll
    for (int n = 0; n < 2; n++) {
        const int doff = dys[n] * 32 + dxs[n];           // compile-time constant
        bool ok = ((unsigned)(y + dys[n]) < 32u) & ((unsigned)(x + dxs[n]) < 32u);
        const int po = ok ? doff * ROW_U2 : 0;
        bi[0][n] = ok ? 0.0f : -100.0f;
        vb[0][n][0] = qr[po + lane];
        vb[0][n][1] = qr[po + 16 + lane];
    }

    #pragma unroll
    for (int p = 0; p < 6; p++) {
        const int cur = p & 1, nxt = cur ^ 1;

        // Prefetch next pair (hides L1/L2 latency under this pair's math)
        if (p < 5) {
            #pragma unroll
            for (int n = 0; n < 2; n++) {
                const int t = (p + 1) * 2 + n;
                const int doff = dys[t] * 32 + dxs[t];   // compile-time constant
                bool ok = ((unsigned)(y + dys[t]) < 32u) & ((unsigned)(x + dxs[t]) < 32u);
                const int po = ok ? doff * ROW_U2 : 0;
                bi[nxt][n] = ok ? 0.0f : -100.0f;
                vb[nxt][n][0] = qr[po + lane];
                vb[nxt][n][1] = qr[po + 16 + lane];
            }
        }

        // Packed partial dot products q.v and norms v.v (4 FFMA2 each)
        float dpn[2], sqn[2];
        #pragma unroll
        for (int n = 0; n < 2; n++) {
            const unsigned long long v00 = vb[cur][n][0].x, v01 = vb[cur][n][0].y;
            const unsigned long long v10 = vb[cur][n][1].x, v11 = vb[cur][n][1].y;
            unsigned long long d2 = pk_mul(q0.x, v00);
            unsigned long long s2 = pk_mul(v00, v00);
            d2 = pk_fma(q0.y, v01, d2);
            s2 = pk_fma(v01, v01, s2);
            d2 = pk_fma(q1.x, v10, d2);
            s2 = pk_fma(v10, v10, s2);
            d2 = pk_fma(q1.y, v11, d2);
            s2 = pk_fma(v11, v11, s2);
            dpn[n] = pk_hadd(d2);
            sqn[n] = pk_hadd(s2);
        }

        // 16-lane butterfly reduce: 4 independent chains, stages interleaved
        #pragma unroll
        for (int m = 1; m < 16; m <<= 1) {
            dpn[0] += __shfl_xor_sync(0xffffffffu, dpn[0], m);
            sqn[0] += __shfl_xor_sync(0xffffffffu, sqn[0], m);
            dpn[1] += __shfl_xor_sync(0xffffffffu, dpn[1], m);
            sqn[1] += __shfl_xor_sync(0xffffffffu, sqn[1], m);
        }

        // w = 2^( dp * rsqrt(|v|^2) * C + bias );  OOB bias -100 -> w ~ 0
        #pragma unroll
        for (int n = 0; n < 2; n++) {
            float sc = rsqrt_approx(sqn[n]) * C_SC;
            float w = ex2_approx(fmaf(dpn[n], sc, bi[cur][n]));
            ssum += w;
            const unsigned long long w2 = pk2(w, w);
            a00 = pk_fma(w2, vb[cur][n][0].x, a00);
            a01 = pk_fma(w2, vb[cur][n][0].y, a01);
            a10 = pk_fma(w2, vb[cur][n][1].x, a10);
            a11 = pk_fma(w2, vb[cur][n][1].y, a11);
        }
    }

    const float inv = 1.0f / ssum;
    const unsigned long long inv2 = pk2(inv, inv);
    ulonglong2 o0, o1;
    o0.x = pk_mul(a00, inv2);
    o0.y = pk_mul(a01, inv2);
    o1.x = pk_mul(a10, inv2);
    o1.y = pk_mul(a11, inv2);

    ulonglong2* orow = (ulonglong2*)(out + ((size_t)(b * N_TOK + i) * L_DIM + l) * D_DIM);
    orow[lane] = o0;
    orow[16 + lane] = o1;
}

extern "C" void kernel_launch(void* const* d_in, const int* in_sizes, int n_in,
                              void* d_out, int out_size) {
    const float* in = (const float*)d_in[0];
    float* out = (float*)d_out;
    attn_kernel<<<ROWS / 8, 128>>>(in, out);   // 6144 blocks, 8 tokens each
}

// round 7
// speedup vs baseline: 2.1535x; 1.0983x over previous
#include <cuda_runtime.h>

// ConsensusAttention: levels [B=8, N=1024, L=6, D=128] fp32.
// Local attention: each token attends to <=13 neighbors (dy^2+dx^2 <= 4 on 32x32 grid),
// self sim fixed at -0.0005, others = (q_i . k_j)/sqrt(D) with k = normalized levels.
// Single fused kernel. 8 lanes/token, 4 tokens/warp: every SHFL serves 4 tokens,
// every LDG.128 instruction covers one full 128B line per token (perfect coalescing).
// Neighbor norms computed in-flight; softmax weight via one EX2.

#define B_DIM 8
#define N_TOK 1024
#define L_DIM 6
#define D_DIM 128
#define ROWS (B_DIM * N_TOK * L_DIM)   // 49152
#define ROW_STRIDE (L_DIM * D_DIM)     // 768 floats between consecutive j
#define ROW_U2 (ROW_STRIDE / 4)        // 192 ulonglong2 per row

// ---- packed f32x2 helpers (Blackwell FFMA2 path, PTX-only) ----
__device__ __forceinline__ unsigned long long pk2(float lo, float hi) {
    unsigned long long r;
    asm("mov.b64 %0, {%1, %2};" : "=l"(r) : "f"(lo), "f"(hi));
    return r;
}
__device__ __forceinline__ unsigned long long pk_fma(unsigned long long a,
                                                     unsigned long long b,
                                                     unsigned long long c) {
    unsigned long long d;
    asm("fma.rn.f32x2 %0, %1, %2, %3;" : "=l"(d) : "l"(a), "l"(b), "l"(c));
    return d;
}
__device__ __forceinline__ unsigned long long pk_mul(unsigned long long a,
                                                     unsigned long long b) {
    unsigned long long d;
    asm("mul.rn.f32x2 %0, %1, %2;" : "=l"(d) : "l"(a), "l"(b));
    return d;
}
__device__ __forceinline__ float pk_hadd(unsigned long long a) {
    float lo, hi;
    asm("mov.b64 {%0, %1}, %2;" : "=f"(lo), "=f"(hi) : "l"(a));
    return lo + hi;
}
__device__ __forceinline__ float rsqrt_approx(float x) {
    float r;
    asm("rsqrt.approx.f32 %0, %1;" : "=f"(r) : "f"(x));
    return r;
}
__device__ __forceinline__ float ex2_approx(float x) {
    float r;
    asm("ex2.approx.f32 %0, %1;" : "=f"(r) : "f"(x));
    return r;
}

// 8 lanes/token; lane owns floats {k*32 + lane*4 .. +3 : k=0..3} (fixed
// permutation; store uses the same pattern). One neighbor per pipeline step,
// double-buffered.
__global__ __launch_bounds__(256, 3) void attn_kernel(const float* __restrict__ in,
                                                      float* __restrict__ out) {
    const int tid  = threadIdx.x;
    const int gid  = (blockIdx.x * 256 + tid) >> 3;  // token id, 0..49151
    const int lane = tid & 7;

    const int i  = gid & (N_TOK - 1);
    const int bl = gid >> 10;          // b * L + l
    const int b  = bl / L_DIM;
    const int l  = bl - b * L_DIM;
    const int y  = i >> 5;
    const int x  = i & 31;

    // self row pointer; neighbor j = i + doff is at qr + doff*ROW_U2
    const ulonglong2* qr =
        (const ulonglong2*)(in + ((size_t)b * N_TOK * L_DIM + l) * D_DIM
                               + (size_t)i * ROW_STRIDE);

    ulonglong2 q[4];
    #pragma unroll
    for (int k = 0; k < 4; k++) q[k] = qr[k * 8 + lane];

    // Self term: sim = -0.0005 exactly; value = q.
    const float wself = 0.9995001249791693f;   // exp(-0.0005)
    float ssum = wself;
    const unsigned long long ws2 = pk2(wself, wself);
    unsigned long long acc[8];
    #pragma unroll
    for (int k = 0; k < 4; k++) {
        acc[2 * k]     = pk_mul(ws2, q[k].x);
        acc[2 * k + 1] = pk_mul(ws2, q[k].y);
    }

    // 12 non-self neighbors with dy^2 + dx^2 <= 4
    const int dys[12] = {-2, -1, -1, -1,  0,  0, 0, 0, 1, 1, 1, 2};
    const int dxs[12] = { 0, -1,  0,  1, -2, -1, 1, 2,-1, 0, 1, 0};
    // sim->exp2 scale: (1/sqrt(128)) * log2(e)
    const float C_SC = 0.12751742119567576f;

    ulonglong2 vb[2][4];   // [parity][d-chunk]
    float      bi[2];      // exp2 bias: 0, or -100 if OOB (ex2 -> ~0)

    // Prologue: load neighbor 0
    {
        const int doff = dys[0] * 32 + dxs[0];
        bool ok = ((unsigned)(y + dys[0]) < 32u) & ((unsigned)(x + dxs[0]) < 32u);
        const int po = ok ? doff * ROW_U2 : 0;
        bi[0] = ok ? 0.0f : -100.0f;
        #pragma unroll
        for (int k = 0; k < 4; k++) vb[0][k] = qr[po + k * 8 + lane];
    }

    #pragma unroll
    for (int t = 0; t < 12; t++) {
        const int cur = t & 1, nxt = cur ^ 1;

        // Prefetch next neighbor (hides L1/L2 latency under this one's math)
        if (t < 11) {
            const int doff = dys[t + 1] * 32 + dxs[t + 1];   // compile-time constant
            bool ok = ((unsigned)(y + dys[t + 1]) < 32u) & ((unsigned)(x + dxs[t + 1]) < 32u);
            const int po = ok ? doff * ROW_U2 : 0;
            bi[nxt] = ok ? 0.0f : -100.0f;
            #pragma unroll
            for (int k = 0; k < 4; k++) vb[nxt][k] = qr[po + k * 8 + lane];
        }

        // Packed partial dot product q.v and norm v.v (8 FFMA2 each)
        unsigned long long d2 = pk_mul(q[0].x, vb[cur][0].x);
        unsigned long long s2 = pk_mul(vb[cur][0].x, vb[cur][0].x);
        d2 = pk_fma(q[0].y, vb[cur][0].y, d2);
        s2 = pk_fma(vb[cur][0].y, vb[cur][0].y, s2);
        #pragma unroll
        for (int k = 1; k < 4; k++) {
            d2 = pk_fma(q[k].x, vb[cur][k].x, d2);
            s2 = pk_fma(vb[cur][k].x, vb[cur][k].x, s2);
            d2 = pk_fma(q[k].y, vb[cur][k].y, d2);
            s2 = pk_fma(vb[cur][k].y, vb[cur][k].y, s2);
        }
        float dp = pk_hadd(d2);
        float sq = pk_hadd(s2);

        // 8-lane butterfly reduce (each SHFL serves all 4 tokens in the warp)
        #pragma unroll
        for (int m = 1; m < 8; m <<= 1) {
            dp += __shfl_xor_sync(0xffffffffu, dp, m);
            sq += __shfl_xor_sync(0xffffffffu, sq, m);
        }

        // w = 2^( dp * rsqrt(|v|^2) * C + bias );  OOB bias -100 -> w ~ 0
        float sc = rsqrt_approx(sq) * C_SC;
        float w  = ex2_approx(fmaf(dp, sc, bi[cur]));
        ssum += w;
        const unsigned long long w2 = pk2(w, w);
        #pragma unroll
        for (int k = 0; k < 4; k++) {
            acc[2 * k]     = pk_fma(w2, vb[cur][k].x, acc[2 * k]);
            acc[2 * k + 1] = pk_fma(w2, vb[cur][k].y, acc[2 * k + 1]);
        }
    }

    const float inv = 1.0f / ssum;
    const unsigned long long inv2 = pk2(inv, inv);
    ulonglong2* orow = (ulonglong2*)(out + ((size_t)(b * N_TOK + i) * L_DIM + l) * D_DIM);
    #pragma unroll
    for (int k = 0; k < 4; k++) {
        ulonglong2 o;
        o.x = pk_mul(acc[2 * k], inv2);
        o.y = pk_mul(acc[2 * k + 1], inv2);
        orow[k * 8 + lane] = o;
    }
}

extern "C" void kernel_launch(void* const* d_in, const int* in_sizes, int n_in,
                              void* d_out, int out_size) {
    const float* in = (const float*)d_in[0];
    float* out = (float*)d_out;
    attn_kernel<<<ROWS / 32, 256>>>(in, out);   // 1536 blocks, 32 tokens each
}